// round 12
// baseline (speedup 1.0000x reference)
#include <cuda_runtime.h>
#include <cuda_fp16.h>
#include <cstdint>
#include <math.h>

#define B_SZ   1024
#define RANK   256
#define NENT   100000
#define MAXNB  50

// GEMM tiling: 128x256 tile, K = 2 chunks of 128 halves, 2-stage ring flowing
// across tiles (persistent CTAs), cp.async.bulk + mbarrier feed.
#define BM 128
#define BN 256
#define BKC 128
#define KP 136
#define ROW_BYTES 256
#define A_STG (BM * KP * 2)
#define B_STG (BN * KP * 2)
#define STG_BYTES (A_STG + B_STG)
#define SM_CTRL 128
#define SMEM_BYTES (SM_CTRL + 2 * STG_BYTES)   // 209024
#define NT (8 * 391)
#define NBT 391
#define CHUNK_TX ((BM + BN) * ROW_BYTES)

#define QSCALE 524288.0f
#define RSCALE 512.0f
#define OSCALE 3.725290298461914e-09f

// prep smem layout (floats, within the dynamic smem block)
#define P_TRP   0
#define P_WSM   4096
#define P_LR    6144
#define P_WPART 8192
#define P_MDEN  12288
#define P_SC    12320
#define P_RED   12336
#define P_GSM   12400
#define PREP_BLOCKS 128

// scratch + sync state (allocation-free rule: device globals)
__device__ __align__(16) __half g_q16[B_SZ * RANK];
__device__ __align__(16) __half g_rhs16[(size_t)NENT * RANK];
__device__ int g_flag_q[8];
__device__ int g_flag_b[NBT];       // 0 = todo, 1 = in progress, 2 = done
__device__ unsigned int g_conv_ctr;

__device__ __forceinline__ void mma_f16(float* c, const uint32_t* a, uint32_t b0, uint32_t b1) {
    asm volatile(
        "mma.sync.aligned.m16n8k16.row.col.f32.f16.f16.f32 "
        "{%0,%1,%2,%3}, {%4,%5,%6,%7}, {%8,%9}, {%0,%1,%2,%3};\n"
        : "+f"(c[0]), "+f"(c[1]), "+f"(c[2]), "+f"(c[3])
        : "r"(a[0]), "r"(a[1]), "r"(a[2]), "r"(a[3]), "r"(b0), "r"(b1));
}
__device__ __forceinline__ void ldsm_x4(uint32_t* r, uint32_t addr) {
    asm volatile("ldmatrix.sync.aligned.m8n8.x4.shared.b16 {%0,%1,%2,%3}, [%4];"
                 : "=r"(r[0]), "=r"(r[1]), "=r"(r[2]), "=r"(r[3]) : "r"(addr));
}
__device__ __forceinline__ void bulk_cp(uint32_t dst, const void* src, uint32_t bytes,
                                        uint32_t mbar) {
    asm volatile(
        "cp.async.bulk.shared::cluster.global.mbarrier::complete_tx::bytes "
        "[%0], [%1], %2, [%3];"
        :: "r"(dst), "l"(src), "r"(bytes), "r"(mbar) : "memory");
}
__device__ __forceinline__ int ld_acquire(const int* p) {
    int v;
    asm volatile("ld.acquire.gpu.global.b32 %0, [%1];" : "=r"(v) : "l"(p));
    return v;
}
#define MBARRIER_INIT(a, cnt) \
    asm volatile("mbarrier.init.shared.b64 [%0], %1;" \
                 :: "r"((uint32_t)(a)), "r"((uint32_t)(cnt)) : "memory")
#define MBARRIER_EXPECT_TX(a, bytes) \
    asm volatile("mbarrier.arrive.expect_tx.shared.b64 _, [%0], %1;" \
                 :: "r"((uint32_t)(a)), "r"((uint32_t)(bytes)) : "memory")
#define MBARRIER_WAIT_PARITY(a, par) do {                                        \
    uint32_t _m = (uint32_t)(a), _p = (uint32_t)(par), _d;                       \
    asm volatile("{\n\t.reg .pred p;\n\t"                                        \
        "mbarrier.try_wait.parity.acquire.cta.shared::cta.b64 p, [%1], %2;\n\t"  \
        "selp.b32 %0, 1, 0, p;\n\t}" : "=r"(_d) : "r"(_m), "r"(_p) : "memory");  \
    if (!_d) {                                                                   \
        asm volatile("{\n\t.reg .pred P1;\n\t"                                   \
            "WL_%=:\n\t"                                                         \
            "mbarrier.try_wait.parity.acquire.cta.shared::cta.b64 P1, [%0], %1, 0x989680;\n\t" \
            "@P1 bra.uni WD_%=;\n\tbra.uni WL_%=;\n\tWD_%=:\n\t}"                \
            :: "r"(_m), "r"(_p) : "memory");                                     \
    }                                                                            \
} while (0)

// ---------------------------------------------------------------------------
// Kernel 0: reset sync state (graph-replay safe)
// ---------------------------------------------------------------------------
__global__ void reset_kernel() {
    int i = threadIdx.x;
    if (i < 8) g_flag_q[i] = 0;
    for (int u = i; u < NBT; u += 256) g_flag_b[u] = 0;
    if (i == 0) g_conv_ctr = 0u;
}

// ---------------------------------------------------------------------------
// Kernel 1 (fused, persistent): prep (CTAs 0-127) -> flag-gated persistent
// GEMM with convert-on-demand / work-stealing B conversion (all CTAs).
// ---------------------------------------------------------------------------
__global__ __launch_bounds__(512, 1) void fused_kernel(
    const int* __restrict__ x, const int* __restrict__ nb_idx,
    const float* __restrict__ lhs_w, const float* __restrict__ rel_w,
    const float* __restrict__ rhs_w,
    const float* __restrict__ W_w, const float* __restrict__ W_b,
    const float* __restrict__ W2_w, const float* __restrict__ W2_b,
    const float* __restrict__ Wo_w, const float* __restrict__ Wo_b,
    const float* __restrict__ Uo_w, const float* __restrict__ Uo_b,
    float* __restrict__ out, float* __restrict__ aux)
{
    extern __shared__ char dynsm[];
    float* sm = reinterpret_cast<float*>(dynsm);
    __shared__ int sh_st;

    const int tid = threadIdx.x;
    const int lane = tid & 31;
    const int warp = tid >> 5;

    // ===================== Phase 1: prep (CTAs 0..127) =====================
    if (blockIdx.x < PREP_BLOCKS) {
        float* trp    = sm + P_TRP;
        float* w_sm   = sm + P_WSM;
        float* lr_sm  = sm + P_LR;
        float* w_part = sm + P_WPART;
        float* mden   = sm + P_MDEN;
        float* scb    = sm + P_SC;
        float* red    = sm + P_RED;
        float* g_sm   = sm + P_GSM;

        const int b0 = blockIdx.x * 8;
        const int grp = tid >> 8;
        const int t2 = tid & 255;

#pragma unroll
        for (int r = 0; r < 4; r++) {
            int bb = grp * 4 + r;
            int b = b0 + bb;
            int i0 = x[b * 3 + 0];
            int i1 = x[b * 3 + 1];
            int i2 = x[b * 3 + 2];
            float lv = lhs_w[(size_t)i0 * RANK + t2];
            float rv = rel_w[(size_t)i1 * RANK + t2];
            float hv = rhs_w[(size_t)i2 * RANK + t2];
            trp[bb * 512 + t2]       = lv;
            trp[bb * 512 + 256 + t2] = rv;
            lr_sm[bb * 256 + t2] = lv * rv;
            if (aux) {
                aux[(size_t)b * RANK + t2]              = lv;
                aux[262144 + (size_t)b * RANK + t2]     = rv;
                aux[2 * 262144 + (size_t)b * RANK + t2] = hv;
            }
        }
        __syncthreads();

        // w = trp_E @ W_w.T + W_b (direct rows, i-split across groups)
        {
            float acc[8];
#pragma unroll
            for (int bb = 0; bb < 8; bb++) acc[bb] = 0.f;
            const float* wrow = W_w + (size_t)t2 * 512 + grp * 256;
            for (int i = 0; i < 256; i += 4) {
                float4 wv = *reinterpret_cast<const float4*>(wrow + i);
#pragma unroll
                for (int bb = 0; bb < 8; bb++) {
                    const float4 tv = *reinterpret_cast<const float4*>(&trp[bb * 512 + grp * 256 + i]);
                    acc[bb] += wv.x * tv.x + wv.y * tv.y + wv.z * tv.z + wv.w * tv.w;
                }
            }
#pragma unroll
            for (int bb = 0; bb < 8; bb++) w_part[(grp * 8 + bb) * 256 + t2] = acc[bb];
        }
        __syncthreads();
        if (tid < 256) {
            float bias = W_b[t2];
#pragma unroll
            for (int bb = 0; bb < 8; bb++)
                w_sm[bb * 256 + t2] = w_part[bb * 256 + t2] + w_part[(8 + bb) * 256 + t2] + bias;
        }
        __syncthreads();

        // attention: 2 warps/row, 25 neighbors each, prefetched online softmax
        {
            const int bb = warp >> 1;
            const int h = warp & 1;
            const int b = b0 + bb;
            float wreg[8];
#pragma unroll
            for (int j = 0; j < 8; j++) wreg[j] = w_sm[bb * 256 + lane + 32 * j];
            float ctx_acc[8];
#pragma unroll
            for (int j = 0; j < 8; j++) ctx_acc[j] = 0.f;
            float Mx = -1e30f, den = 0.f;
            const int mbase = b * MAXNB + h * 25;

            float rv[8];
            {
                int nb0 = __ldg(&nb_idx[mbase]);
                const float* rc = rhs_w + (size_t)nb0 * RANK;
#pragma unroll
                for (int j = 0; j < 8; j++) rv[j] = __ldg(&rc[lane + 32 * j]);
            }
            for (int m = 0; m < 25; m++) {
                float nx[8];
                if (m < 24) {
                    int nbn = __ldg(&nb_idx[mbase + m + 1]);
                    const float* rn = rhs_w + (size_t)nbn * RANK;
#pragma unroll
                    for (int j = 0; j < 8; j++) nx[j] = __ldg(&rn[lane + 32 * j]);
                }
                float s = 0.f;
#pragma unroll
                for (int j = 0; j < 8; j++) s += wreg[j] * rv[j];
#pragma unroll
                for (int o = 16; o > 0; o >>= 1) s += __shfl_xor_sync(0xffffffffu, s, o);
                float Mn = fmaxf(Mx, s);
                float scale = __expf(Mx - Mn);
                float p = __expf(s - Mn);
                den = den * scale + p;
#pragma unroll
                for (int j = 0; j < 8; j++) ctx_acc[j] = ctx_acc[j] * scale + p * rv[j];
                Mx = Mn;
                if (m < 24) {
#pragma unroll
                    for (int j = 0; j < 8; j++) rv[j] = nx[j];
                }
            }
#pragma unroll
            for (int j = 0; j < 8; j++) trp[warp * 256 + lane + 32 * j] = ctx_acc[j];
            if (lane == 0) { mden[warp * 2 + 0] = Mx; mden[warp * 2 + 1] = den; }
        }
        __syncthreads();
        if (tid < 8) {
            float M0 = mden[(2 * tid) * 2 + 0],     d0 = mden[(2 * tid) * 2 + 1];
            float M1 = mden[(2 * tid + 1) * 2 + 0], d1 = mden[(2 * tid + 1) * 2 + 1];
            float M = fmaxf(M0, M1);
            float s0 = __expf(M0 - M), s1 = __expf(M1 - M);
            float inv = 1.f / (d0 * s0 + d1 * s1);
            scb[tid * 2 + 0] = s0 * inv;
            scb[tid * 2 + 1] = s1 * inv;
        }
        __syncthreads();
#pragma unroll
        for (int p = 0; p < 4; p++) {
            int idx = tid + p * 512;
            int bb = idx >> 8, t = idx & 255;
            w_part[bb * 256 + t] = trp[(2 * bb) * 256 + t] * scb[bb * 2 + 0]
                                 + trp[(2 * bb + 1) * 256 + t] * scb[bb * 2 + 1];
        }
        __syncthreads();

        // e_c matvec (direct rows, k-split across groups)
        {
            float acc[8];
#pragma unroll
            for (int bb = 0; bb < 8; bb++) acc[bb] = 0.f;
            const float* w2row = W2_w + (size_t)t2 * 256 + grp * 128;
            for (int k = 0; k < 128; k += 4) {
                float4 wv = *reinterpret_cast<const float4*>(w2row + k);
#pragma unroll
                for (int bb = 0; bb < 8; bb++) {
                    const float4 cv = *reinterpret_cast<const float4*>(&w_part[bb * 256 + grp * 128 + k]);
                    acc[bb] += wv.x * cv.x + wv.y * cv.y + wv.z * cv.z + wv.w * cv.w;
                }
            }
#pragma unroll
            for (int bb = 0; bb < 8; bb++) trp[(grp * 8 + bb) * 256 + t2] = acc[bb];
        }
        __syncthreads();

        float ec[8];
        if (tid < 256) {
            float bias = W2_b[t2];
#pragma unroll
            for (int bb = 0; bb < 8; bb++) {
                ec[bb] = trp[bb * 256 + t2] + trp[(8 + bb) * 256 + t2] + bias;
                if (aux) aux[3 * 262144 + (size_t)(b0 + bb) * RANK + t2] = ec[bb];
            }
            float uo = Uo_w[t2], wo = Wo_w[t2];
#pragma unroll
            for (int bb = 0; bb < 8; bb++) {
                float c = uo * lr_sm[bb * 256 + t2] + wo * ec[bb];
#pragma unroll
                for (int o = 16; o > 0; o >>= 1) c += __shfl_xor_sync(0xffffffffu, c, o);
                if (lane == 0) red[bb * 8 + warp] = c;
            }
        }
        __syncthreads();
        if (tid < 8) {
            float s = 0.f;
#pragma unroll
            for (int w = 0; w < 8; w++) s += red[tid * 8 + w];
            s += Uo_b[0] + Wo_b[0];
            g_sm[tid] = 1.f / (1.f + expf(-s));
        }
        __syncthreads();
        if (tid < 256) {
#pragma unroll
            for (int bb = 0; bb < 8; bb++) {
                float g = g_sm[bb];
                float q = lr_sm[bb * 256 + t2] * (g * ec[bb] + 1.f - g);
                g_q16[(size_t)(b0 + bb) * RANK + t2] = __float2half_rn(q * QSCALE);
            }
        }
        __threadfence();
        __syncthreads();
        if (tid == 0) atomicAdd(&g_flag_q[blockIdx.x >> 4], 1);
    }

    // ============ Phase 2: persistent GEMM + convert-on-demand ==============
    const int wm = warp & 1;     // m offset 64*wm
    const int wn = warp >> 1;    // n offset 32*wn
    const int gid = lane >> 2;
    const int qid = lane & 3;
    const int lrow = lane & 15;
    const int lcol16 = (lane >> 4) * 16;

    const uint32_t smem_u32 = (uint32_t)__cvta_generic_to_shared(dynsm);
    const uint32_t mbar0 = smem_u32;

    const int nct = gridDim.x;
    const int nloc = (NT - (int)blockIdx.x + nct - 1) / nct;
    if (nloc <= 0) return;
    const int Ltot = 2 * nloc;

    // block-wide: convert one 256-row B unit, then mark done
    auto convert_unit = [&](int u) {
        int r0 = u * 256;
        int nrows = NENT - r0;
        if (nrows > 256) nrows = 256;
        for (int i = tid; i < nrows * 32; i += 512) {
            int row = i >> 5, c8 = (i & 31) * 8;
            size_t base = (size_t)(r0 + row) * RANK + c8;
            float4 v0 = *reinterpret_cast<const float4*>(rhs_w + base);
            float4 v1 = *reinterpret_cast<const float4*>(rhs_w + base + 4);
            __half2 h[4];
            h[0] = __floats2half2_rn(v0.x * RSCALE, v0.y * RSCALE);
            h[1] = __floats2half2_rn(v0.z * RSCALE, v0.w * RSCALE);
            h[2] = __floats2half2_rn(v1.x * RSCALE, v1.y * RSCALE);
            h[3] = __floats2half2_rn(v1.z * RSCALE, v1.w * RSCALE);
            *reinterpret_cast<uint4*>(g_rhs16 + base) = *reinterpret_cast<uint4*>(h);
        }
        __threadfence();
        __syncthreads();
        if (tid == 0) atomicExch(&g_flag_b[u], 2);
    };

    // block-wide: wait until tile t's A (prep) and B (converted) are ready,
    // stealing convert work while the prep wait is unmet.
    auto ensure_tile = [&](int t) {
        const int mt = t & 7, nt = t >> 3;
        for (;;) {
            if (tid == 0) {
                if (ld_acquire(&g_flag_q[mt]) >= 16) sh_st = -1;        // A ready
                else {
                    unsigned u = atomicAdd(&g_conv_ctr, 1u);
                    sh_st = (u < (unsigned)NBT &&
                             atomicCAS(&g_flag_b[u], 0, 1) == 0) ? (int)u : -2;
                }
            }
            __syncthreads();
            int s = sh_st;
            __syncthreads();
            if (s == -1) break;
            if (s >= 0) convert_unit(s);
        }
        for (;;) {
            if (tid == 0) {
                int s = ld_acquire(&g_flag_b[nt]);
                if (s == 0) s = (atomicCAS(&g_flag_b[nt], 0, 1) == 0) ? 3 : 1;
                sh_st = s;
            }
            __syncthreads();
            int s = sh_st;
            __syncthreads();
            if (s == 2) break;
            if (s == 3) { convert_unit(nt); break; }
        }
    };

    auto issue_chunk = [&](int L) {
        const int li = L >> 1, ch = L & 1;
        const int t = (int)blockIdx.x + li * nct;
        const int m0 = (t & 7) * BM;
        const int n0 = (t >> 3) * BN;
        const uint32_t sb = smem_u32 + SM_CTRL + (uint32_t)(ch * STG_BYTES);
        const uint32_t mb = mbar0 + ch * 8;
        if (tid < BM)
            bulk_cp(sb + (uint32_t)(tid * KP * 2),
                    g_q16 + (size_t)(m0 + tid) * RANK + ch * BKC, ROW_BYTES, mb);
        if (tid < BN) {
            int nr = n0 + tid;
            if (nr > NENT - 1) nr = NENT - 1;
            bulk_cp(sb + A_STG + (uint32_t)(tid * KP * 2),
                    g_rhs16 + (size_t)nr * RANK + ch * BKC, ROW_BYTES, mb);
        }
    };

    __syncthreads();
    if (tid == 0) {
        MBARRIER_INIT(mbar0 + 0, 1);
        MBARRIER_INIT(mbar0 + 8, 1);
    }
    __syncthreads();
    ensure_tile((int)blockIdx.x);
    if (tid == 0) {
        MBARRIER_EXPECT_TX(mbar0 + 0, CHUNK_TX);
        if (Ltot > 1) MBARRIER_EXPECT_TX(mbar0 + 8, CHUNK_TX);
    }
    __syncthreads();
    issue_chunk(0);
    if (Ltot > 1) issue_chunk(1);

#pragma unroll 1
    for (int li = 0; li < nloc; li++) {
        const int t = (int)blockIdx.x + li * nct;
        const int m0 = (t & 7) * BM;
        const int n0 = (t >> 3) * BN;

        float acc[4][4][4];
#pragma unroll
        for (int i = 0; i < 4; i++)
#pragma unroll
            for (int f = 0; f < 4; f++)
#pragma unroll
                for (int r = 0; r < 4; r++) acc[i][f][r] = 0.f;

#pragma unroll 1
        for (int ch = 0; ch < 2; ch++) {
            const int L = li * 2 + ch;
            MBARRIER_WAIT_PARITY(mbar0 + ch * 8, li & 1);

            const uint32_t abase = smem_u32 + SM_CTRL + (uint32_t)(ch * STG_BYTES);
            const uint32_t bbase = abase + A_STG;
#pragma unroll
            for (int kk = 0; kk < BKC / 16; kk++) {
                uint32_t a[4][4];
#pragma unroll
                for (int i = 0; i < 4; i++)
                    ldsm_x4(a[i], abase + (uint32_t)((wm * 64 + i * 16 + lrow) * (KP * 2)
                                                     + kk * 32 + lcol16));
                uint32_t b[2][4];
#pragma unroll
                for (int j = 0; j < 2; j++)
                    ldsm_x4(b[j], bbase + (uint32_t)((wn * 32 + j * 16 + lrow) * (KP * 2)
                                                     + kk * 32 + lcol16));
#pragma unroll
                for (int i = 0; i < 4; i++)
#pragma unroll
                    for (int f = 0; f < 4; f++) {
                        int j = f >> 1, h = f & 1;
                        mma_f16(acc[i][f], a[i], b[j][h], b[j][h + 2]);
                    }
            }

            if (L + 2 < Ltot) {
                __syncthreads();
                if (ch == 0) ensure_tile((int)blockIdx.x + (li + 1) * nct);
                if (tid == 0) MBARRIER_EXPECT_TX(mbar0 + ch * 8, CHUNK_TX);
                __syncthreads();
                issue_chunk(L + 2);
            }
        }

        // epilogue: descale + streaming stores
#pragma unroll
        for (int i = 0; i < 4; i++) {
            int r = m0 + wm * 64 + i * 16 + gid;
#pragma unroll
            for (int f = 0; f < 4; f++) {
                int cb = n0 + wn * 32 + f * 8 + 2 * qid;
                if (cb < NENT) {
                    __stcs(reinterpret_cast<float2*>(out + (size_t)r * NENT + cb),
                           make_float2(acc[i][f][0] * OSCALE, acc[i][f][1] * OSCALE));
                    __stcs(reinterpret_cast<float2*>(out + (size_t)(r + 8) * NENT + cb),
                           make_float2(acc[i][f][2] * OSCALE, acc[i][f][3] * OSCALE));
                }
            }
        }
    }
}

// ---------------------------------------------------------------------------
extern "C" void kernel_launch(void* const* d_in, const int* in_sizes, int n_in,
                              void* d_out, int out_size) {
    const int*   x      = (const int*)d_in[0];
    const int*   nb     = (const int*)d_in[1];
    const float* lhs_w  = (const float*)d_in[2];
    const float* rel_w  = (const float*)d_in[3];
    const float* rhs_w  = (const float*)d_in[4];
    const float* W_w    = (const float*)d_in[5];
    const float* W_b    = (const float*)d_in[6];
    const float* W2_w   = (const float*)d_in[7];
    const float* W2_b   = (const float*)d_in[8];
    const float* Wo_w   = (const float*)d_in[9];
    const float* Wo_b   = (const float*)d_in[10];
    const float* Uo_w   = (const float*)d_in[11];
    const float* Uo_b   = (const float*)d_in[12];
    float* out = (float*)d_out;

    float* aux = nullptr;
    if (out_size >= 102400000 + 4 * 262144) aux = out + 102400000;

    static int nsm = 0;
    if (!nsm) {
        cudaFuncSetAttribute(fused_kernel,
                             cudaFuncAttributeMaxDynamicSharedMemorySize, SMEM_BYTES);
        int dev = 0;
        cudaGetDevice(&dev);
        cudaDeviceGetAttribute(&nsm, cudaDevAttrMultiProcessorCount, dev);
        if (nsm <= 0) nsm = 148;
        if (nsm > 1024) nsm = 1024;
    }

    reset_kernel<<<1, 256>>>();
    fused_kernel<<<nsm, 512, SMEM_BYTES>>>(x, nb, lhs_w, rel_w, rhs_w,
                                           W_w, W_b, W2_w, W2_b,
                                           Wo_w, Wo_b, Uo_w, Uo_b, out, aux);
}

// round 13
// speedup vs baseline: 1.1175x; 1.1175x over previous
#include <cuda_runtime.h>
#include <cuda_fp16.h>
#include <cstdint>
#include <math.h>

#define B_SZ   1024
#define RANK   256
#define NENT   100000
#define MAXNB  50

// GEMM tiling: 128x256 tile, K = 2 chunks of 128 halves, 2-stage ring flowing
// across tiles (persistent CTAs, contiguous tile ranges), bulk-cp + mbarrier.
#define BM 128
#define BN 256
#define BKC 128
#define KP 136
#define ROW_BYTES 256
#define A_STG (BM * KP * 2)
#define B_STG (BN * KP * 2)
#define STG_BYTES (A_STG + B_STG)
#define SM_CTRL 128
#define SMEM_BYTES (SM_CTRL + 2 * STG_BYTES)   // 209024
#define NT (8 * 391)
#define NBT 391
#define CHUNK_TX ((BM + BN) * ROW_BYTES)

#define QSCALE 524288.0f
#define RSCALE 512.0f
#define OSCALE 3.725290298461914e-09f

// prep smem layout (floats, within the dynamic smem block)
#define P_TRP   0
#define P_WSM   4096
#define P_LR    6144
#define P_WPART 8192
#define P_MDEN  12288
#define P_SC    12320
#define P_RED   12336
#define P_GSM   12400
#define PREP_BLOCKS 128

// scratch + sync state (allocation-free rule: device globals)
__device__ __align__(16) __half g_q16[B_SZ * RANK];
__device__ __align__(16) __half g_rhs16[(size_t)NENT * RANK];
__device__ int g_flag_q[8];
__device__ int g_flag_b[NBT];       // 0 = todo, 1 = in progress, 2 = done

__device__ __forceinline__ void mma_f16(float* c, const uint32_t* a, uint32_t b0, uint32_t b1) {
    asm volatile(
        "mma.sync.aligned.m16n8k16.row.col.f32.f16.f16.f32 "
        "{%0,%1,%2,%3}, {%4,%5,%6,%7}, {%8,%9}, {%0,%1,%2,%3};\n"
        : "+f"(c[0]), "+f"(c[1]), "+f"(c[2]), "+f"(c[3])
        : "r"(a[0]), "r"(a[1]), "r"(a[2]), "r"(a[3]), "r"(b0), "r"(b1));
}
__device__ __forceinline__ void ldsm_x4(uint32_t* r, uint32_t addr) {
    asm volatile("ldmatrix.sync.aligned.m8n8.x4.shared.b16 {%0,%1,%2,%3}, [%4];"
                 : "=r"(r[0]), "=r"(r[1]), "=r"(r[2]), "=r"(r[3]) : "r"(addr));
}
__device__ __forceinline__ void bulk_cp(uint32_t dst, const void* src, uint32_t bytes,
                                        uint32_t mbar) {
    asm volatile(
        "cp.async.bulk.shared::cluster.global.mbarrier::complete_tx::bytes "
        "[%0], [%1], %2, [%3];"
        :: "r"(dst), "l"(src), "r"(bytes), "r"(mbar) : "memory");
}
__device__ __forceinline__ int ld_acquire(const int* p) {
    int v;
    asm volatile("ld.acquire.gpu.global.b32 %0, [%1];" : "=r"(v) : "l"(p));
    return v;
}
#define MBARRIER_INIT(a, cnt) \
    asm volatile("mbarrier.init.shared.b64 [%0], %1;" \
                 :: "r"((uint32_t)(a)), "r"((uint32_t)(cnt)) : "memory")
#define MBARRIER_EXPECT_TX(a, bytes) \
    asm volatile("mbarrier.arrive.expect_tx.shared.b64 _, [%0], %1;" \
                 :: "r"((uint32_t)(a)), "r"((uint32_t)(bytes)) : "memory")
#define MBARRIER_WAIT_PARITY(a, par) do {                                        \
    uint32_t _m = (uint32_t)(a), _p = (uint32_t)(par), _d;                       \
    asm volatile("{\n\t.reg .pred p;\n\t"                                        \
        "mbarrier.try_wait.parity.acquire.cta.shared::cta.b64 p, [%1], %2;\n\t"  \
        "selp.b32 %0, 1, 0, p;\n\t}" : "=r"(_d) : "r"(_m), "r"(_p) : "memory");  \
    if (!_d) {                                                                   \
        asm volatile("{\n\t.reg .pred P1;\n\t"                                   \
            "WL_%=:\n\t"                                                         \
            "mbarrier.try_wait.parity.acquire.cta.shared::cta.b64 P1, [%0], %1, 0x989680;\n\t" \
            "@P1 bra.uni WD_%=;\n\tbra.uni WL_%=;\n\tWD_%=:\n\t}"                \
            :: "r"(_m), "r"(_p) : "memory");                                     \
    }                                                                            \
} while (0)

// ---------------------------------------------------------------------------
// Kernel 0: reset sync state (graph-replay safe)
// ---------------------------------------------------------------------------
__global__ void reset_kernel() {
    int i = threadIdx.x;
    if (i < 8) g_flag_q[i] = 0;
    for (int u = i; u < NBT; u += 256) g_flag_b[u] = 0;
}

// ---------------------------------------------------------------------------
// Kernel 1 (fused, persistent): prep (CTAs 0-127) -> own-range B convert ->
// flag-gated persistent GEMM over a contiguous tile range.
// ---------------------------------------------------------------------------
__global__ __launch_bounds__(512, 1) void fused_kernel(
    const int* __restrict__ x, const int* __restrict__ nb_idx,
    const float* __restrict__ lhs_w, const float* __restrict__ rel_w,
    const float* __restrict__ rhs_w,
    const float* __restrict__ W_w, const float* __restrict__ W_b,
    const float* __restrict__ W2_w, const float* __restrict__ W2_b,
    const float* __restrict__ Wo_w, const float* __restrict__ Wo_b,
    const float* __restrict__ Uo_w, const float* __restrict__ Uo_b,
    float* __restrict__ out, float* __restrict__ aux)
{
    extern __shared__ char dynsm[];
    float* sm = reinterpret_cast<float*>(dynsm);
    __shared__ int sh_st;

    const int tid = threadIdx.x;
    const int lane = tid & 31;
    const int warp = tid >> 5;

    // ===================== Phase 1: prep (CTAs 0..127) =====================
    if (blockIdx.x < PREP_BLOCKS) {
        float* trp    = sm + P_TRP;
        float* w_sm   = sm + P_WSM;
        float* lr_sm  = sm + P_LR;
        float* w_part = sm + P_WPART;
        float* mden   = sm + P_MDEN;
        float* scb    = sm + P_SC;
        float* red    = sm + P_RED;
        float* g_sm   = sm + P_GSM;

        const int b0 = blockIdx.x * 8;
        const int grp = tid >> 8;
        const int t2 = tid & 255;

#pragma unroll
        for (int r = 0; r < 4; r++) {
            int bb = grp * 4 + r;
            int b = b0 + bb;
            int i0 = x[b * 3 + 0];
            int i1 = x[b * 3 + 1];
            int i2 = x[b * 3 + 2];
            float lv = lhs_w[(size_t)i0 * RANK + t2];
            float rv = rel_w[(size_t)i1 * RANK + t2];
            float hv = rhs_w[(size_t)i2 * RANK + t2];
            trp[bb * 512 + t2]       = lv;
            trp[bb * 512 + 256 + t2] = rv;
            lr_sm[bb * 256 + t2] = lv * rv;
            if (aux) {
                aux[(size_t)b * RANK + t2]              = lv;
                aux[262144 + (size_t)b * RANK + t2]     = rv;
                aux[2 * 262144 + (size_t)b * RANK + t2] = hv;
            }
        }
        __syncthreads();

        // w = trp_E @ W_w.T + W_b (direct rows, i-split across groups)
        {
            float acc[8];
#pragma unroll
            for (int bb = 0; bb < 8; bb++) acc[bb] = 0.f;
            const float* wrow = W_w + (size_t)t2 * 512 + grp * 256;
            for (int i = 0; i < 256; i += 4) {
                float4 wv = *reinterpret_cast<const float4*>(wrow + i);
#pragma unroll
                for (int bb = 0; bb < 8; bb++) {
                    const float4 tv = *reinterpret_cast<const float4*>(&trp[bb * 512 + grp * 256 + i]);
                    acc[bb] += wv.x * tv.x + wv.y * tv.y + wv.z * tv.z + wv.w * tv.w;
                }
            }
#pragma unroll
            for (int bb = 0; bb < 8; bb++) w_part[(grp * 8 + bb) * 256 + t2] = acc[bb];
        }
        __syncthreads();
        if (tid < 256) {
            float bias = W_b[t2];
#pragma unroll
            for (int bb = 0; bb < 8; bb++)
                w_sm[bb * 256 + t2] = w_part[bb * 256 + t2] + w_part[(8 + bb) * 256 + t2] + bias;
        }
        __syncthreads();

        // attention: 2 warps/row, 25 neighbors each, prefetched online softmax
        {
            const int bb = warp >> 1;
            const int h = warp & 1;
            const int b = b0 + bb;
            float wreg[8];
#pragma unroll
            for (int j = 0; j < 8; j++) wreg[j] = w_sm[bb * 256 + lane + 32 * j];
            float ctx_acc[8];
#pragma unroll
            for (int j = 0; j < 8; j++) ctx_acc[j] = 0.f;
            float Mx = -1e30f, den = 0.f;
            const int mbase = b * MAXNB + h * 25;

            float rv[8];
            {
                int nb0 = __ldg(&nb_idx[mbase]);
                const float* rc = rhs_w + (size_t)nb0 * RANK;
#pragma unroll
                for (int j = 0; j < 8; j++) rv[j] = __ldg(&rc[lane + 32 * j]);
            }
            for (int m = 0; m < 25; m++) {
                float nx[8];
                if (m < 24) {
                    int nbn = __ldg(&nb_idx[mbase + m + 1]);
                    const float* rn = rhs_w + (size_t)nbn * RANK;
#pragma unroll
                    for (int j = 0; j < 8; j++) nx[j] = __ldg(&rn[lane + 32 * j]);
                }
                float s = 0.f;
#pragma unroll
                for (int j = 0; j < 8; j++) s += wreg[j] * rv[j];
#pragma unroll
                for (int o = 16; o > 0; o >>= 1) s += __shfl_xor_sync(0xffffffffu, s, o);
                float Mn = fmaxf(Mx, s);
                float scale = __expf(Mx - Mn);
                float p = __expf(s - Mn);
                den = den * scale + p;
#pragma unroll
                for (int j = 0; j < 8; j++) ctx_acc[j] = ctx_acc[j] * scale + p * rv[j];
                Mx = Mn;
                if (m < 24) {
#pragma unroll
                    for (int j = 0; j < 8; j++) rv[j] = nx[j];
                }
            }
#pragma unroll
            for (int j = 0; j < 8; j++) trp[warp * 256 + lane + 32 * j] = ctx_acc[j];
            if (lane == 0) { mden[warp * 2 + 0] = Mx; mden[warp * 2 + 1] = den; }
        }
        __syncthreads();
        if (tid < 8) {
            float M0 = mden[(2 * tid) * 2 + 0],     d0 = mden[(2 * tid) * 2 + 1];
            float M1 = mden[(2 * tid + 1) * 2 + 0], d1 = mden[(2 * tid + 1) * 2 + 1];
            float M = fmaxf(M0, M1);
            float s0 = __expf(M0 - M), s1 = __expf(M1 - M);
            float inv = 1.f / (d0 * s0 + d1 * s1);
            scb[tid * 2 + 0] = s0 * inv;
            scb[tid * 2 + 1] = s1 * inv;
        }
        __syncthreads();
#pragma unroll
        for (int p = 0; p < 4; p++) {
            int idx = tid + p * 512;
            int bb = idx >> 8, t = idx & 255;
            w_part[bb * 256 + t] = trp[(2 * bb) * 256 + t] * scb[bb * 2 + 0]
                                 + trp[(2 * bb + 1) * 256 + t] * scb[bb * 2 + 1];
        }
        __syncthreads();

        // e_c matvec (direct rows, k-split across groups)
        {
            float acc[8];
#pragma unroll
            for (int bb = 0; bb < 8; bb++) acc[bb] = 0.f;
            const float* w2row = W2_w + (size_t)t2 * 256 + grp * 128;
            for (int k = 0; k < 128; k += 4) {
                float4 wv = *reinterpret_cast<const float4*>(w2row + k);
#pragma unroll
                for (int bb = 0; bb < 8; bb++) {
                    const float4 cv = *reinterpret_cast<const float4*>(&w_part[bb * 256 + grp * 128 + k]);
                    acc[bb] += wv.x * cv.x + wv.y * cv.y + wv.z * cv.z + wv.w * cv.w;
                }
            }
#pragma unroll
            for (int bb = 0; bb < 8; bb++) trp[(grp * 8 + bb) * 256 + t2] = acc[bb];
        }
        __syncthreads();

        float ec[8];
        if (tid < 256) {
            float bias = W2_b[t2];
#pragma unroll
            for (int bb = 0; bb < 8; bb++) {
                ec[bb] = trp[bb * 256 + t2] + trp[(8 + bb) * 256 + t2] + bias;
                if (aux) aux[3 * 262144 + (size_t)(b0 + bb) * RANK + t2] = ec[bb];
            }
            float uo = Uo_w[t2], wo = Wo_w[t2];
#pragma unroll
            for (int bb = 0; bb < 8; bb++) {
                float c = uo * lr_sm[bb * 256 + t2] + wo * ec[bb];
#pragma unroll
                for (int o = 16; o > 0; o >>= 1) c += __shfl_xor_sync(0xffffffffu, c, o);
                if (lane == 0) red[bb * 8 + warp] = c;
            }
        }
        __syncthreads();
        if (tid < 8) {
            float s = 0.f;
#pragma unroll
            for (int w = 0; w < 8; w++) s += red[tid * 8 + w];
            s += Uo_b[0] + Wo_b[0];
            g_sm[tid] = 1.f / (1.f + expf(-s));
        }
        __syncthreads();
        if (tid < 256) {
#pragma unroll
            for (int bb = 0; bb < 8; bb++) {
                float g = g_sm[bb];
                float q = lr_sm[bb * 256 + t2] * (g * ec[bb] + 1.f - g);
                g_q16[(size_t)(b0 + bb) * RANK + t2] = __float2half_rn(q * QSCALE);
            }
        }
        __threadfence();
        __syncthreads();
        if (tid == 0) atomicAdd(&g_flag_q[blockIdx.x >> 4], 1);
    }

    // ======== Phase 2: convert own B units, then persistent GEMM ===========
    const int wm = warp & 1;     // m offset 64*wm
    const int wn = warp >> 1;    // n offset 32*wn
    const int gid = lane >> 2;
    const int qid = lane & 3;
    const int lrow = lane & 15;
    const int lcol16 = (lane >> 4) * 16;

    const uint32_t smem_u32 = (uint32_t)__cvta_generic_to_shared(dynsm);
    const uint32_t mbar0 = smem_u32;

    const int nct = gridDim.x;
    const int t0 = (int)(((long long)blockIdx.x * NT) / nct);
    const int t1 = (int)(((long long)(blockIdx.x + 1) * NT) / nct);
    const int nloc = t1 - t0;
    if (nloc <= 0) return;
    const int Ltot = 2 * nloc;

    // block-wide: convert one 256-row B unit, mark done
    auto convert_unit = [&](int u) {
        int r0 = u * 256;
        int nrows = NENT - r0;
        if (nrows > 256) nrows = 256;
        for (int i = tid; i < nrows * 32; i += 512) {
            int row = i >> 5, c8 = (i & 31) * 8;
            size_t base = (size_t)(r0 + row) * RANK + c8;
            float4 v0 = *reinterpret_cast<const float4*>(rhs_w + base);
            float4 v1 = *reinterpret_cast<const float4*>(rhs_w + base + 4);
            __half2 h[4];
            h[0] = __floats2half2_rn(v0.x * RSCALE, v0.y * RSCALE);
            h[1] = __floats2half2_rn(v0.z * RSCALE, v0.w * RSCALE);
            h[2] = __floats2half2_rn(v1.x * RSCALE, v1.y * RSCALE);
            h[3] = __floats2half2_rn(v1.z * RSCALE, v1.w * RSCALE);
            *reinterpret_cast<uint4*>(g_rhs16 + base) = *reinterpret_cast<uint4*>(h);
        }
        __threadfence();
        __syncthreads();
        if (tid == 0) atomicExch(&g_flag_b[u], 2);
    };

    // convert all B units my tile range touches (CAS-claimed, parallel chip-wide)
    {
        const int u0 = t0 >> 3, u1 = (t1 - 1) >> 3;
        for (int u = u0; u <= u1; u++) {
            if (tid == 0) sh_st = (atomicCAS(&g_flag_b[u], 0, 1) == 0) ? 1 : 0;
            __syncthreads();
            int claim = sh_st;
            __syncthreads();
            if (claim) convert_unit(u);
            __syncthreads();
        }
    }

    auto wait_tile = [&](int t) {
        if (tid == 0) {
            int mt = t & 7, nt = t >> 3;
            while (ld_acquire(&g_flag_q[mt]) < 16) {}
            while (ld_acquire(&g_flag_b[nt]) != 2) {}
        }
        __syncthreads();
    };
    auto issue_chunk = [&](int L) {
        const int li = L >> 1, ch = L & 1;
        const int t = t0 + li;
        const int m0 = (t & 7) * BM;
        const int n0 = (t >> 3) * BN;
        const uint32_t sb = smem_u32 + SM_CTRL + (uint32_t)(ch * STG_BYTES);
        const uint32_t mb = mbar0 + ch * 8;
        if (tid < BM)
            bulk_cp(sb + (uint32_t)(tid * KP * 2),
                    g_q16 + (size_t)(m0 + tid) * RANK + ch * BKC, ROW_BYTES, mb);
        if (tid < BN) {
            int nr = n0 + tid;
            if (nr > NENT - 1) nr = NENT - 1;
            bulk_cp(sb + A_STG + (uint32_t)(tid * KP * 2),
                    g_rhs16 + (size_t)nr * RANK + ch * BKC, ROW_BYTES, mb);
        }
    };

    if (tid == 0) {
        MBARRIER_INIT(mbar0 + 0, 1);
        MBARRIER_INIT(mbar0 + 8, 1);
    }
    __syncthreads();
    wait_tile(t0);
    if (tid == 0) {
        MBARRIER_EXPECT_TX(mbar0 + 0, CHUNK_TX);
        if (Ltot > 1) MBARRIER_EXPECT_TX(mbar0 + 8, CHUNK_TX);
    }
    __syncthreads();
    issue_chunk(0);
    if (Ltot > 1) issue_chunk(1);

#pragma unroll 1
    for (int li = 0; li < nloc; li++) {
        const int t = t0 + li;
        const int m0 = (t & 7) * BM;
        const int n0 = (t >> 3) * BN;

        float acc[4][4][4];
#pragma unroll
        for (int i = 0; i < 4; i++)
#pragma unroll
            for (int f = 0; f < 4; f++)
#pragma unroll
                for (int r = 0; r < 4; r++) acc[i][f][r] = 0.f;

#pragma unroll 1
        for (int ch = 0; ch < 2; ch++) {
            const int L = li * 2 + ch;
            MBARRIER_WAIT_PARITY(mbar0 + ch * 8, li & 1);

            const uint32_t abase = smem_u32 + SM_CTRL + (uint32_t)(ch * STG_BYTES);
            const uint32_t bbase = abase + A_STG;
#pragma unroll
            for (int kk = 0; kk < BKC / 16; kk++) {
                uint32_t a[4][4];
#pragma unroll
                for (int i = 0; i < 4; i++)
                    ldsm_x4(a[i], abase + (uint32_t)((wm * 64 + i * 16 + lrow) * (KP * 2)
                                                     + kk * 32 + lcol16));
                uint32_t b[2][4];
#pragma unroll
                for (int j = 0; j < 2; j++)
                    ldsm_x4(b[j], bbase + (uint32_t)((wn * 32 + j * 16 + lrow) * (KP * 2)
                                                     + kk * 32 + lcol16));
#pragma unroll
                for (int i = 0; i < 4; i++)
#pragma unroll
                    for (int f = 0; f < 4; f++) {
                        int j = f >> 1, h = f & 1;
                        mma_f16(acc[i][f], a[i], b[j][h], b[j][h + 2]);
                    }
            }

            if (L + 2 < Ltot) {
                __syncthreads();
                if (ch == 0) wait_tile(t0 + li + 1);
                if (tid == 0) MBARRIER_EXPECT_TX(mbar0 + ch * 8, CHUNK_TX);
                __syncthreads();
                issue_chunk(L + 2);
            }
        }

        // epilogue: descale + streaming stores
#pragma unroll
        for (int i = 0; i < 4; i++) {
            int r = m0 + wm * 64 + i * 16 + gid;
#pragma unroll
            for (int f = 0; f < 4; f++) {
                int cb = n0 + wn * 32 + f * 8 + 2 * qid;
                if (cb < NENT) {
                    __stcs(reinterpret_cast<float2*>(out + (size_t)r * NENT + cb),
                           make_float2(acc[i][f][0] * OSCALE, acc[i][f][1] * OSCALE));
                    __stcs(reinterpret_cast<float2*>(out + (size_t)(r + 8) * NENT + cb),
                           make_float2(acc[i][f][2] * OSCALE, acc[i][f][3] * OSCALE));
                }
            }
        }
    }
}

// ---------------------------------------------------------------------------
extern "C" void kernel_launch(void* const* d_in, const int* in_sizes, int n_in,
                              void* d_out, int out_size) {
    const int*   x      = (const int*)d_in[0];
    const int*   nb     = (const int*)d_in[1];
    const float* lhs_w  = (const float*)d_in[2];
    const float* rel_w  = (const float*)d_in[3];
    const float* rhs_w  = (const float*)d_in[4];
    const float* W_w    = (const float*)d_in[5];
    const float* W_b    = (const float*)d_in[6];
    const float* W2_w   = (const float*)d_in[7];
    const float* W2_b   = (const float*)d_in[8];
    const float* Wo_w   = (const float*)d_in[9];
    const float* Wo_b   = (const float*)d_in[10];
    const float* Uo_w   = (const float*)d_in[11];
    const float* Uo_b   = (const float*)d_in[12];
    float* out = (float*)d_out;

    float* aux = nullptr;
    if (out_size >= 102400000 + 4 * 262144) aux = out + 102400000;

    static int nsm = 0;
    if (!nsm) {
        cudaFuncSetAttribute(fused_kernel,
                             cudaFuncAttributeMaxDynamicSharedMemorySize, SMEM_BYTES);
        int dev = 0;
        cudaGetDevice(&dev);
        cudaDeviceGetAttribute(&nsm, cudaDevAttrMultiProcessorCount, dev);
        if (nsm <= 0) nsm = 148;
        if (nsm > 1024) nsm = 1024;
    }

    reset_kernel<<<1, 256>>>();
    fused_kernel<<<nsm, 512, SMEM_BYTES>>>(x, nb, lhs_w, rel_w, rhs_w,
                                           W_w, W_b, W2_w, W2_b,
                                           Wo_w, Wo_b, Uo_w, Uo_b, out, aux);
}

// round 14
// speedup vs baseline: 1.1770x; 1.0533x over previous
#include <cuda_runtime.h>
#include <cuda_fp16.h>
#include <cstdint>
#include <math.h>

#define B_SZ   1024
#define RANK   256
#define NENT   100000
#define MAXNB  50

// GEMM tiling: 128x256 tile, K = 2 chunks of 128 halves, 2-stage ring flowing
// across tiles (persistent CTAs), cp.async.bulk + mbarrier feed.
#define BM 128
#define BN 256
#define BKC 128
#define KP 136
#define ROW_BYTES 256
#define A_STG (BM * KP * 2)
#define B_STG (BN * KP * 2)
#define STG_BYTES (A_STG + B_STG)
#define SM_CTRL 128
#define SMEM_BYTES (SM_CTRL + 2 * STG_BYTES)   // 209024
#define NT (8 * 391)
#define NBT 391
#define CHUNK_TX ((BM + BN) * ROW_BYTES)

#define QSCALE 524288.0f
#define RSCALE 512.0f
#define OSCALE 3.725290298461914e-09f

// prep smem layout (floats, within the dynamic smem block)
#define P_TRP   0
#define P_WSM   4096
#define P_LR    6144
#define P_WPART 8192
#define P_MDEN  12288
#define P_SC    12320
#define P_RED   12336
#define P_GSM   12400
#define PREP_BLOCKS 128

// scratch + sync state (allocation-free rule: device globals)
__device__ __align__(16) __half g_q16[B_SZ * RANK];
__device__ __align__(16) __half g_rhs16[(size_t)NENT * RANK];
__device__ int g_flag_q[8];
__device__ int g_flag_b[NBT];       // 0 = todo, 1 = done
__device__ unsigned int g_conv_ctr;

__device__ __forceinline__ void mma_f16(float* c, const uint32_t* a, uint32_t b0, uint32_t b1) {
    asm volatile(
        "mma.sync.aligned.m16n8k16.row.col.f32.f16.f16.f32 "
        "{%0,%1,%2,%3}, {%4,%5,%6,%7}, {%8,%9}, {%0,%1,%2,%3};\n"
        : "+f"(c[0]), "+f"(c[1]), "+f"(c[2]), "+f"(c[3])
        : "r"(a[0]), "r"(a[1]), "r"(a[2]), "r"(a[3]), "r"(b0), "r"(b1));
}
__device__ __forceinline__ void ldsm_x4(uint32_t* r, uint32_t addr) {
    asm volatile("ldmatrix.sync.aligned.m8n8.x4.shared.b16 {%0,%1,%2,%3}, [%4];"
                 : "=r"(r[0]), "=r"(r[1]), "=r"(r[2]), "=r"(r[3]) : "r"(addr));
}
__device__ __forceinline__ void bulk_cp(uint32_t dst, const void* src, uint32_t bytes,
                                        uint32_t mbar) {
    asm volatile(
        "cp.async.bulk.shared::cluster.global.mbarrier::complete_tx::bytes "
        "[%0], [%1], %2, [%3];"
        :: "r"(dst), "l"(src), "r"(bytes), "r"(mbar) : "memory");
}
__device__ __forceinline__ int ld_acquire(const int* p) {
    int v;
    asm volatile("ld.acquire.gpu.global.b32 %0, [%1];" : "=r"(v) : "l"(p));
    return v;
}
#define MBARRIER_INIT(a, cnt) \
    asm volatile("mbarrier.init.shared.b64 [%0], %1;" \
                 :: "r"((uint32_t)(a)), "r"((uint32_t)(cnt)) : "memory")
#define MBARRIER_EXPECT_TX(a, bytes) \
    asm volatile("mbarrier.arrive.expect_tx.shared.b64 _, [%0], %1;" \
                 :: "r"((uint32_t)(a)), "r"((uint32_t)(bytes)) : "memory")
#define MBARRIER_WAIT_PARITY(a, par) do {                                        \
    uint32_t _m = (uint32_t)(a), _p = (uint32_t)(par), _d;                       \
    asm volatile("{\n\t.reg .pred p;\n\t"                                        \
        "mbarrier.try_wait.parity.acquire.cta.shared::cta.b64 p, [%1], %2;\n\t"  \
        "selp.b32 %0, 1, 0, p;\n\t}" : "=r"(_d) : "r"(_m), "r"(_p) : "memory");  \
    if (!_d) {                                                                   \
        asm volatile("{\n\t.reg .pred P1;\n\t"                                   \
            "WL_%=:\n\t"                                                         \
            "mbarrier.try_wait.parity.acquire.cta.shared::cta.b64 P1, [%0], %1, 0x989680;\n\t" \
            "@P1 bra.uni WD_%=;\n\tbra.uni WL_%=;\n\tWD_%=:\n\t}"                \
            :: "r"(_m), "r"(_p) : "memory");                                     \
    }                                                                            \
} while (0)

// ---------------------------------------------------------------------------
// Kernel 0: reset sync state (graph-replay safe)
// ---------------------------------------------------------------------------
__global__ void reset_kernel() {
    int i = threadIdx.x;
    if (i < 8) g_flag_q[i] = 0;
    for (int u = i; u < NBT; u += 256) g_flag_b[u] = 0;
    if (i == 0) g_conv_ctr = 0u;
}

// ---------------------------------------------------------------------------
// Kernel 1 (fused, persistent): prep (CTAs 0-127) -> convert queue (all) ->
// flag-gated persistent GEMM (all CTAs).
// ---------------------------------------------------------------------------
__global__ __launch_bounds__(512, 1) void fused_kernel(
    const int* __restrict__ x, const int* __restrict__ nb_idx,
    const float* __restrict__ lhs_w, const float* __restrict__ rel_w,
    const float* __restrict__ rhs_w,
    const float* __restrict__ W_w, const float* __restrict__ W_b,
    const float* __restrict__ W2_w, const float* __restrict__ W2_b,
    const float* __restrict__ Wo_w, const float* __restrict__ Wo_b,
    const float* __restrict__ Uo_w, const float* __restrict__ Uo_b,
    float* __restrict__ out, float* __restrict__ aux)
{
    extern __shared__ char dynsm[];
    float* sm = reinterpret_cast<float*>(dynsm);
    __shared__ unsigned cu;

    const int tid = threadIdx.x;
    const int lane = tid & 31;
    const int warp = tid >> 5;

    // ===================== Phase 1: prep (CTAs 0..127) =====================
    if (blockIdx.x < PREP_BLOCKS) {
        float* trp    = sm + P_TRP;
        float* w_sm   = sm + P_WSM;
        float* lr_sm  = sm + P_LR;
        float* w_part = sm + P_WPART;
        float* mden   = sm + P_MDEN;
        float* scb    = sm + P_SC;
        float* red    = sm + P_RED;
        float* g_sm   = sm + P_GSM;

        const int b0 = blockIdx.x * 8;
        const int grp = tid >> 8;
        const int t2 = tid & 255;

#pragma unroll
        for (int r = 0; r < 4; r++) {
            int bb = grp * 4 + r;
            int b = b0 + bb;
            int i0 = x[b * 3 + 0];
            int i1 = x[b * 3 + 1];
            int i2 = x[b * 3 + 2];
            float lv = lhs_w[(size_t)i0 * RANK + t2];
            float rv = rel_w[(size_t)i1 * RANK + t2];
            float hv = rhs_w[(size_t)i2 * RANK + t2];
            trp[bb * 512 + t2]       = lv;
            trp[bb * 512 + 256 + t2] = rv;
            lr_sm[bb * 256 + t2] = lv * rv;
            if (aux) {
                __stcs(&aux[(size_t)b * RANK + t2], lv);
                __stcs(&aux[262144 + (size_t)b * RANK + t2], rv);
                __stcs(&aux[2 * 262144 + (size_t)b * RANK + t2], hv);
            }
        }
        __syncthreads();

        // w = trp_E @ W_w.T + W_b (direct rows, i-split across groups)
        {
            float acc[8];
#pragma unroll
            for (int bb = 0; bb < 8; bb++) acc[bb] = 0.f;
            const float* wrow = W_w + (size_t)t2 * 512 + grp * 256;
            for (int i = 0; i < 256; i += 4) {
                float4 wv = *reinterpret_cast<const float4*>(wrow + i);
#pragma unroll
                for (int bb = 0; bb < 8; bb++) {
                    const float4 tv = *reinterpret_cast<const float4*>(&trp[bb * 512 + grp * 256 + i]);
                    acc[bb] += wv.x * tv.x + wv.y * tv.y + wv.z * tv.z + wv.w * tv.w;
                }
            }
#pragma unroll
            for (int bb = 0; bb < 8; bb++) w_part[(grp * 8 + bb) * 256 + t2] = acc[bb];
        }
        __syncthreads();
        if (tid < 256) {
            float bias = W_b[t2];
#pragma unroll
            for (int bb = 0; bb < 8; bb++)
                w_sm[bb * 256 + t2] = w_part[bb * 256 + t2] + w_part[(8 + bb) * 256 + t2] + bias;
        }
        __syncthreads();

        // attention: 2 warps/row, 25 neighbors each, prefetched online softmax
        {
            const int bb = warp >> 1;
            const int h = warp & 1;
            const int b = b0 + bb;
            float wreg[8];
#pragma unroll
            for (int j = 0; j < 8; j++) wreg[j] = w_sm[bb * 256 + lane + 32 * j];
            float ctx_acc[8];
#pragma unroll
            for (int j = 0; j < 8; j++) ctx_acc[j] = 0.f;
            float Mx = -1e30f, den = 0.f;
            const int mbase = b * MAXNB + h * 25;

            float rv[8];
            {
                int nb0 = __ldg(&nb_idx[mbase]);
                const float* rc = rhs_w + (size_t)nb0 * RANK;
#pragma unroll
                for (int j = 0; j < 8; j++) rv[j] = __ldg(&rc[lane + 32 * j]);
            }
            for (int m = 0; m < 25; m++) {
                float nx[8];
                if (m < 24) {
                    int nbn = __ldg(&nb_idx[mbase + m + 1]);
                    const float* rn = rhs_w + (size_t)nbn * RANK;
#pragma unroll
                    for (int j = 0; j < 8; j++) nx[j] = __ldg(&rn[lane + 32 * j]);
                }
                float s = 0.f;
#pragma unroll
                for (int j = 0; j < 8; j++) s += wreg[j] * rv[j];
#pragma unroll
                for (int o = 16; o > 0; o >>= 1) s += __shfl_xor_sync(0xffffffffu, s, o);
                float Mn = fmaxf(Mx, s);
                float scale = __expf(Mx - Mn);
                float p = __expf(s - Mn);
                den = den * scale + p;
#pragma unroll
                for (int j = 0; j < 8; j++) ctx_acc[j] = ctx_acc[j] * scale + p * rv[j];
                Mx = Mn;
                if (m < 24) {
#pragma unroll
                    for (int j = 0; j < 8; j++) rv[j] = nx[j];
                }
            }
#pragma unroll
            for (int j = 0; j < 8; j++) trp[warp * 256 + lane + 32 * j] = ctx_acc[j];
            if (lane == 0) { mden[warp * 2 + 0] = Mx; mden[warp * 2 + 1] = den; }
        }
        __syncthreads();
        if (tid < 8) {
            float M0 = mden[(2 * tid) * 2 + 0],     d0 = mden[(2 * tid) * 2 + 1];
            float M1 = mden[(2 * tid + 1) * 2 + 0], d1 = mden[(2 * tid + 1) * 2 + 1];
            float M = fmaxf(M0, M1);
            float s0 = __expf(M0 - M), s1 = __expf(M1 - M);
            float inv = 1.f / (d0 * s0 + d1 * s1);
            scb[tid * 2 + 0] = s0 * inv;
            scb[tid * 2 + 1] = s1 * inv;
        }
        __syncthreads();
#pragma unroll
        for (int p = 0; p < 4; p++) {
            int idx = tid + p * 512;
            int bb = idx >> 8, t = idx & 255;
            w_part[bb * 256 + t] = trp[(2 * bb) * 256 + t] * scb[bb * 2 + 0]
                                 + trp[(2 * bb + 1) * 256 + t] * scb[bb * 2 + 1];
        }
        __syncthreads();

        // e_c matvec (direct rows, k-split across groups)
        {
            float acc[8];
#pragma unroll
            for (int bb = 0; bb < 8; bb++) acc[bb] = 0.f;
            const float* w2row = W2_w + (size_t)t2 * 256 + grp * 128;
            for (int k = 0; k < 128; k += 4) {
                float4 wv = *reinterpret_cast<const float4*>(w2row + k);
#pragma unroll
                for (int bb = 0; bb < 8; bb++) {
                    const float4 cv = *reinterpret_cast<const float4*>(&w_part[bb * 256 + grp * 128 + k]);
                    acc[bb] += wv.x * cv.x + wv.y * cv.y + wv.z * cv.z + wv.w * cv.w;
                }
            }
#pragma unroll
            for (int bb = 0; bb < 8; bb++) trp[(grp * 8 + bb) * 256 + t2] = acc[bb];
        }
        __syncthreads();

        float ec[8];
        if (tid < 256) {
            float bias = W2_b[t2];
#pragma unroll
            for (int bb = 0; bb < 8; bb++) {
                ec[bb] = trp[bb * 256 + t2] + trp[(8 + bb) * 256 + t2] + bias;
                if (aux) __stcs(&aux[3 * 262144 + (size_t)(b0 + bb) * RANK + t2], ec[bb]);
            }
            float uo = Uo_w[t2], wo = Wo_w[t2];
#pragma unroll
            for (int bb = 0; bb < 8; bb++) {
                float c = uo * lr_sm[bb * 256 + t2] + wo * ec[bb];
#pragma unroll
                for (int o = 16; o > 0; o >>= 1) c += __shfl_xor_sync(0xffffffffu, c, o);
                if (lane == 0) red[bb * 8 + warp] = c;
            }
        }
        __syncthreads();
        if (tid < 8) {
            float s = 0.f;
#pragma unroll
            for (int w = 0; w < 8; w++) s += red[tid * 8 + w];
            s += Uo_b[0] + Wo_b[0];
            g_sm[tid] = 1.f / (1.f + expf(-s));
        }
        __syncthreads();
        if (tid < 256) {
#pragma unroll
            for (int bb = 0; bb < 8; bb++) {
                float g = g_sm[bb];
                float q = lr_sm[bb * 256 + t2] * (g * ec[bb] + 1.f - g);
                g_q16[(size_t)(b0 + bb) * RANK + t2] = __float2half_rn(q * QSCALE);
            }
        }
        __threadfence();
        __syncthreads();
        if (tid == 0) atomicAdd(&g_flag_q[blockIdx.x >> 4], 1);
    }

    // ===================== Phase 2: convert queue (all CTAs) ================
    for (;;) {
        __syncthreads();
        if (tid == 0) cu = atomicAdd(&g_conv_ctr, 1u);
        __syncthreads();
        unsigned u = cu;
        if (u >= (unsigned)NBT) break;
        int r0 = (int)u * 256;
        int nrows = NENT - r0;
        if (nrows > 256) nrows = 256;
        for (int i = tid; i < nrows * 32; i += 512) {
            int row = i >> 5, c8 = (i & 31) * 8;
            size_t base = (size_t)(r0 + row) * RANK + c8;
            float4 v0 = __ldcs(reinterpret_cast<const float4*>(rhs_w + base));
            float4 v1 = __ldcs(reinterpret_cast<const float4*>(rhs_w + base + 4));
            __half2 h[4];
            h[0] = __floats2half2_rn(v0.x * RSCALE, v0.y * RSCALE);
            h[1] = __floats2half2_rn(v0.z * RSCALE, v0.w * RSCALE);
            h[2] = __floats2half2_rn(v1.x * RSCALE, v1.y * RSCALE);
            h[3] = __floats2half2_rn(v1.z * RSCALE, v1.w * RSCALE);
            *reinterpret_cast<uint4*>(g_rhs16 + base) = *reinterpret_cast<uint4*>(h);
        }
        __threadfence();
        __syncthreads();
        if (tid == 0) atomicExch(&g_flag_b[u], 1);
    }

    // ===================== Phase 3: persistent GEMM (all CTAs) ==============
    const int wm = warp & 1;     // m offset 64*wm
    const int wn = warp >> 1;    // n offset 32*wn
    const int gid = lane >> 2;
    const int qid = lane & 3;
    const int lrow = lane & 15;
    const int lcol16 = (lane >> 4) * 16;

    const uint32_t smem_u32 = (uint32_t)__cvta_generic_to_shared(dynsm);
    const uint32_t mbar0 = smem_u32;

    const int nct = gridDim.x;
    const int nloc = (NT - (int)blockIdx.x + nct - 1) / nct;
    if (nloc <= 0) return;
    const int Ltot = 2 * nloc;

    auto wait_tile = [&](int t) {   // tid 0 only
        int mt = t & 7, nt = t >> 3;
        while (ld_acquire(&g_flag_q[mt]) < 16) {}
        while (ld_acquire(&g_flag_b[nt]) == 0) {}
    };
    auto issue_chunk = [&](int L) {
        const int li = L >> 1, ch = L & 1;
        const int t = (int)blockIdx.x + li * nct;
        const int m0 = (t & 7) * BM;
        const int n0 = (t >> 3) * BN;
        const uint32_t sb = smem_u32 + SM_CTRL + (uint32_t)(ch * STG_BYTES);
        const uint32_t mb = mbar0 + ch * 8;
        if (tid < BM)
            bulk_cp(sb + (uint32_t)(tid * KP * 2),
                    g_q16 + (size_t)(m0 + tid) * RANK + ch * BKC, ROW_BYTES, mb);
        if (tid < BN) {
            int nr = n0 + tid;
            if (nr > NENT - 1) nr = NENT - 1;
            bulk_cp(sb + A_STG + (uint32_t)(tid * KP * 2),
                    g_rhs16 + (size_t)nr * RANK + ch * BKC, ROW_BYTES, mb);
        }
    };

    __syncthreads();
    if (tid == 0) {
        MBARRIER_INIT(mbar0 + 0, 1);
        MBARRIER_INIT(mbar0 + 8, 1);
    }
    __syncthreads();
    if (tid == 0) {
        wait_tile((int)blockIdx.x);
        MBARRIER_EXPECT_TX(mbar0 + 0, CHUNK_TX);
        if (Ltot > 1) MBARRIER_EXPECT_TX(mbar0 + 8, CHUNK_TX);
    }
    __syncthreads();
    issue_chunk(0);
    if (Ltot > 1) issue_chunk(1);

#pragma unroll 1
    for (int li = 0; li < nloc; li++) {
        const int t = (int)blockIdx.x + li * nct;
        const int m0 = (t & 7) * BM;
        const int n0 = (t >> 3) * BN;

        float acc[4][4][4];
#pragma unroll
        for (int i = 0; i < 4; i++)
#pragma unroll
            for (int f = 0; f < 4; f++)
#pragma unroll
                for (int r = 0; r < 4; r++) acc[i][f][r] = 0.f;

#pragma unroll 1
        for (int ch = 0; ch < 2; ch++) {
            const int L = li * 2 + ch;
            MBARRIER_WAIT_PARITY(mbar0 + ch * 8, li & 1);

            const uint32_t abase = smem_u32 + SM_CTRL + (uint32_t)(ch * STG_BYTES);
            const uint32_t bbase = abase + A_STG;
#pragma unroll
            for (int kk = 0; kk < BKC / 16; kk++) {
                uint32_t a[4][4];
#pragma unroll
                for (int i = 0; i < 4; i++)
                    ldsm_x4(a[i], abase + (uint32_t)((wm * 64 + i * 16 + lrow) * (KP * 2)
                                                     + kk * 32 + lcol16));
                uint32_t b[2][4];
#pragma unroll
                for (int j = 0; j < 2; j++)
                    ldsm_x4(b[j], bbase + (uint32_t)((wn * 32 + j * 16 + lrow) * (KP * 2)
                                                     + kk * 32 + lcol16));
#pragma unroll
                for (int i = 0; i < 4; i++)
#pragma unroll
                    for (int f = 0; f < 4; f++) {
                        int j = f >> 1, h = f & 1;
                        mma_f16(acc[i][f], a[i], b[j][h], b[j][h + 2]);
                    }
            }

            if (L + 2 < Ltot) {
                __syncthreads();
                if (tid == 0) {
                    if (ch == 0) wait_tile((int)blockIdx.x + (li + 1) * nct);
                    MBARRIER_EXPECT_TX(mbar0 + ch * 8, CHUNK_TX);
                }
                __syncthreads();
                issue_chunk(L + 2);
            }
        }

        // epilogue: descale + streaming stores
#pragma unroll
        for (int i = 0; i < 4; i++) {
            int r = m0 + wm * 64 + i * 16 + gid;
#pragma unroll
            for (int f = 0; f < 4; f++) {
                int cb = n0 + wn * 32 + f * 8 + 2 * qid;
                if (cb < NENT) {
                    __stcs(reinterpret_cast<float2*>(out + (size_t)r * NENT + cb),
                           make_float2(acc[i][f][0] * OSCALE, acc[i][f][1] * OSCALE));
                    __stcs(reinterpret_cast<float2*>(out + (size_t)(r + 8) * NENT + cb),
                           make_float2(acc[i][f][2] * OSCALE, acc[i][f][3] * OSCALE));
                }
            }
        }
    }
}

// ---------------------------------------------------------------------------
extern "C" void kernel_launch(void* const* d_in, const int* in_sizes, int n_in,
                              void* d_out, int out_size) {
    const int*   x      = (const int*)d_in[0];
    const int*   nb     = (const int*)d_in[1];
    const float* lhs_w  = (const float*)d_in[2];
    const float* rel_w  = (const float*)d_in[3];
    const float* rhs_w  = (const float*)d_in[4];
    const float* W_w    = (const float*)d_in[5];
    const float* W_b    = (const float*)d_in[6];
    const float* W2_w   = (const float*)d_in[7];
    const float* W2_b   = (const float*)d_in[8];
    const float* Wo_w   = (const float*)d_in[9];
    const float* Wo_b   = (const float*)d_in[10];
    const float* Uo_w   = (const float*)d_in[11];
    const float* Uo_b   = (const float*)d_in[12];
    float* out = (float*)d_out;

    float* aux = nullptr;
    if (out_size >= 102400000 + 4 * 262144) aux = out + 102400000;

    static int nsm = 0;
    if (!nsm) {
        cudaFuncSetAttribute(fused_kernel,
                             cudaFuncAttributeMaxDynamicSharedMemorySize, SMEM_BYTES);
        int dev = 0;
        cudaGetDevice(&dev);
        cudaDeviceGetAttribute(&nsm, cudaDevAttrMultiProcessorCount, dev);
        if (nsm <= 0) nsm = 148;
        if (nsm > 1024) nsm = 1024;
    }

    reset_kernel<<<1, 256>>>();
    fused_kernel<<<nsm, 512, SMEM_BYTES>>>(x, nb, lhs_w, rel_w, rhs_w,
                                           W_w, W_b, W2_w, W2_b,
                                           Wo_w, Wo_b, Uo_w, Uo_b, out, aux);
}

// round 15
// speedup vs baseline: 1.2762x; 1.0843x over previous
#include <cuda_runtime.h>
#include <cuda_fp16.h>
#include <cstdint>
#include <math.h>

#define B_SZ   1024
#define RANK   256
#define NENT   100000
#define MAXNB  50

// GEMM tiling: 128x256 tile, K = 2 chunks of 128 halves, 2-stage ring flowing
// across tiles (persistent CTAs), cp.async.bulk + mbarrier feed.
#define BM 128
#define BN 256
#define BKC 128
#define KP 136
#define ROW_BYTES 256
#define A_STG (BM * KP * 2)
#define B_STG (BN * KP * 2)
#define STG_BYTES (A_STG + B_STG)
#define SM_CTRL 128
#define SMEM_BYTES (SM_CTRL + 2 * STG_BYTES)   // 209024
#define NT (8 * 391)
#define NBT 391
#define CHUNK_TX ((BM + BN) * ROW_BYTES)

#define QSCALE 524288.0f
#define RSCALE 512.0f
#define OSCALE 3.725290298461914e-09f

// prep smem layout (floats, within the dynamic smem block)
#define P_TRP   0
#define P_WSM   4096
#define P_LR    6144
#define P_WPART 8192
#define P_MDEN  12288
#define P_SC    12320
#define P_RED   12336
#define P_GSM   12400
#define PREP_BLOCKS 128

// scratch + sync state (allocation-free rule: device globals)
__device__ __align__(16) __half g_q16[B_SZ * RANK];
__device__ __align__(16) __half g_rhs16[(size_t)NENT * RANK];
__device__ __align__(16) float g_Wt[512 * 256];    // W_w transposed
__device__ __align__(16) float g_W2t[256 * 256];   // W2_w transposed
__device__ int g_flag_q[8];
__device__ int g_flag_b[NBT];       // 0 = todo, 1 = done
__device__ unsigned int g_conv_ctr;

__device__ __forceinline__ void mma_f16(float* c, const uint32_t* a, uint32_t b0, uint32_t b1) {
    asm volatile(
        "mma.sync.aligned.m16n8k16.row.col.f32.f16.f16.f32 "
        "{%0,%1,%2,%3}, {%4,%5,%6,%7}, {%8,%9}, {%0,%1,%2,%3};\n"
        : "+f"(c[0]), "+f"(c[1]), "+f"(c[2]), "+f"(c[3])
        : "r"(a[0]), "r"(a[1]), "r"(a[2]), "r"(a[3]), "r"(b0), "r"(b1));
}
__device__ __forceinline__ void ldsm_x4(uint32_t* r, uint32_t addr) {
    asm volatile("ldmatrix.sync.aligned.m8n8.x4.shared.b16 {%0,%1,%2,%3}, [%4];"
                 : "=r"(r[0]), "=r"(r[1]), "=r"(r[2]), "=r"(r[3]) : "r"(addr));
}
__device__ __forceinline__ void bulk_cp(uint32_t dst, const void* src, uint32_t bytes,
                                        uint32_t mbar) {
    asm volatile(
        "cp.async.bulk.shared::cluster.global.mbarrier::complete_tx::bytes "
        "[%0], [%1], %2, [%3];"
        :: "r"(dst), "l"(src), "r"(bytes), "r"(mbar) : "memory");
}
__device__ __forceinline__ int ld_acquire(const int* p) {
    int v;
    asm volatile("ld.acquire.gpu.global.b32 %0, [%1];" : "=r"(v) : "l"(p));
    return v;
}
#define MBARRIER_INIT(a, cnt) \
    asm volatile("mbarrier.init.shared.b64 [%0], %1;" \
                 :: "r"((uint32_t)(a)), "r"((uint32_t)(cnt)) : "memory")
#define MBARRIER_EXPECT_TX(a, bytes) \
    asm volatile("mbarrier.arrive.expect_tx.shared.b64 _, [%0], %1;" \
                 :: "r"((uint32_t)(a)), "r"((uint32_t)(bytes)) : "memory")
#define MBARRIER_WAIT_PARITY(a, par) do {                                        \
    uint32_t _m = (uint32_t)(a), _p = (uint32_t)(par), _d;                       \
    asm volatile("{\n\t.reg .pred p;\n\t"                                        \
        "mbarrier.try_wait.parity.acquire.cta.shared::cta.b64 p, [%1], %2;\n\t"  \
        "selp.b32 %0, 1, 0, p;\n\t}" : "=r"(_d) : "r"(_m), "r"(_p) : "memory");  \
    if (!_d) {                                                                   \
        asm volatile("{\n\t.reg .pred P1;\n\t"                                   \
            "WL_%=:\n\t"                                                         \
            "mbarrier.try_wait.parity.acquire.cta.shared::cta.b64 P1, [%0], %1, 0x989680;\n\t" \
            "@P1 bra.uni WD_%=;\n\tbra.uni WL_%=;\n\tWD_%=:\n\t}"                \
            :: "r"(_m), "r"(_p) : "memory");                                     \
    }                                                                            \
} while (0)

// ---------------------------------------------------------------------------
// Kernel 0: transpose W_w / W2_w (coalesced prep feed) + reset sync state.
// ---------------------------------------------------------------------------
__global__ __launch_bounds__(256) void setup_kernel(const float* __restrict__ W_w,
                                                    const float* __restrict__ W2_w) {
    if (blockIdx.x == 0 && threadIdx.x < 256) {
        int i = threadIdx.x;
        if (i < 8) g_flag_q[i] = 0;
        for (int u = i; u < NBT; u += 256) g_flag_b[u] = 0;
        if (i == 0) g_conv_ctr = 0u;
    }
    int idx = blockIdx.x * 256 + threadIdx.x;
    if (idx < 512 * 256) {
        int i = idx >> 8, j = idx & 255;          // g_Wt[i][j] = W_w[j][i]
        g_Wt[idx] = W_w[j * 512 + i];
    } else {
        int idx2 = idx - 512 * 256;
        if (idx2 < 256 * 256) {
            int k = idx2 >> 8, j = idx2 & 255;    // g_W2t[k][j] = W2_w[j][k]
            g_W2t[idx2] = W2_w[j * 256 + k];
        }
    }
}

// ---------------------------------------------------------------------------
// Kernel 1 (fused, persistent): prep (CTAs 0-127) -> convert queue (all) ->
// flag-gated persistent GEMM (all CTAs).
// ---------------------------------------------------------------------------
__global__ __launch_bounds__(512, 1) void fused_kernel(
    const int* __restrict__ x, const int* __restrict__ nb_idx,
    const float* __restrict__ lhs_w, const float* __restrict__ rel_w,
    const float* __restrict__ rhs_w,
    const float* __restrict__ W_b, const float* __restrict__ W2_b,
    const float* __restrict__ Wo_w, const float* __restrict__ Wo_b,
    const float* __restrict__ Uo_w, const float* __restrict__ Uo_b,
    float* __restrict__ out, float* __restrict__ aux)
{
    extern __shared__ char dynsm[];
    float* sm = reinterpret_cast<float*>(dynsm);
    __shared__ unsigned cu;

    const int tid = threadIdx.x;
    const int lane = tid & 31;
    const int warp = tid >> 5;

    // ===================== Phase 1: prep (CTAs 0..127) =====================
    if (blockIdx.x < PREP_BLOCKS) {
        float* trp    = sm + P_TRP;
        float* w_sm   = sm + P_WSM;
        float* lr_sm  = sm + P_LR;
        float* w_part = sm + P_WPART;
        float* mden   = sm + P_MDEN;
        float* scb    = sm + P_SC;
        float* red    = sm + P_RED;
        float* g_sm   = sm + P_GSM;

        const int b0 = blockIdx.x * 8;
        const int grp = tid >> 8;
        const int t2 = tid & 255;

#pragma unroll
        for (int r = 0; r < 4; r++) {
            int bb = grp * 4 + r;
            int b = b0 + bb;
            int i0 = x[b * 3 + 0];
            int i1 = x[b * 3 + 1];
            int i2 = x[b * 3 + 2];
            float lv = lhs_w[(size_t)i0 * RANK + t2];
            float rv = rel_w[(size_t)i1 * RANK + t2];
            float hv = rhs_w[(size_t)i2 * RANK + t2];
            trp[bb * 512 + t2]       = lv;
            trp[bb * 512 + 256 + t2] = rv;
            lr_sm[bb * 256 + t2] = lv * rv;
            if (aux) {
                __stcs(&aux[(size_t)b * RANK + t2], lv);
                __stcs(&aux[262144 + (size_t)b * RANK + t2], rv);
                __stcs(&aux[2 * 262144 + (size_t)b * RANK + t2], hv);
            }
        }
        __syncthreads();

        // w = trp_E @ W_w.T + W_b (coalesced via g_Wt, i-split across groups)
        {
            float acc[8];
#pragma unroll
            for (int bb = 0; bb < 8; bb++) acc[bb] = 0.f;
            const int i0 = grp * 256;
            for (int i = i0; i < i0 + 256; i += 4) {
                float wv0 = g_Wt[(i + 0) * 256 + t2];
                float wv1 = g_Wt[(i + 1) * 256 + t2];
                float wv2 = g_Wt[(i + 2) * 256 + t2];
                float wv3 = g_Wt[(i + 3) * 256 + t2];
#pragma unroll
                for (int bb = 0; bb < 8; bb++) {
                    const float4 tv = *reinterpret_cast<const float4*>(&trp[bb * 512 + i]);
                    acc[bb] += wv0 * tv.x + wv1 * tv.y + wv2 * tv.z + wv3 * tv.w;
                }
            }
#pragma unroll
            for (int bb = 0; bb < 8; bb++) w_part[(grp * 8 + bb) * 256 + t2] = acc[bb];
        }
        __syncthreads();
        if (tid < 256) {
            float bias = W_b[t2];
#pragma unroll
            for (int bb = 0; bb < 8; bb++)
                w_sm[bb * 256 + t2] = w_part[bb * 256 + t2] + w_part[(8 + bb) * 256 + t2] + bias;
        }
        __syncthreads();

        // attention: 2 warps/row, 25 neighbors each, prefetched online softmax
        {
            const int bb = warp >> 1;
            const int h = warp & 1;
            const int b = b0 + bb;
            float wreg[8];
#pragma unroll
            for (int j = 0; j < 8; j++) wreg[j] = w_sm[bb * 256 + lane + 32 * j];
            float ctx_acc[8];
#pragma unroll
            for (int j = 0; j < 8; j++) ctx_acc[j] = 0.f;
            float Mx = -1e30f, den = 0.f;
            const int mbase = b * MAXNB + h * 25;

            float rv[8];
            {
                int nb0 = __ldg(&nb_idx[mbase]);
                const float* rc = rhs_w + (size_t)nb0 * RANK;
#pragma unroll
                for (int j = 0; j < 8; j++) rv[j] = __ldg(&rc[lane + 32 * j]);
            }
            for (int m = 0; m < 25; m++) {
                float nx[8];
                if (m < 24) {
                    int nbn = __ldg(&nb_idx[mbase + m + 1]);
                    const float* rn = rhs_w + (size_t)nbn * RANK;
#pragma unroll
                    for (int j = 0; j < 8; j++) nx[j] = __ldg(&rn[lane + 32 * j]);
                }
                float s = 0.f;
#pragma unroll
                for (int j = 0; j < 8; j++) s += wreg[j] * rv[j];
#pragma unroll
                for (int o = 16; o > 0; o >>= 1) s += __shfl_xor_sync(0xffffffffu, s, o);
                float Mn = fmaxf(Mx, s);
                float scale = __expf(Mx - Mn);
                float p = __expf(s - Mn);
                den = den * scale + p;
#pragma unroll
                for (int j = 0; j < 8; j++) ctx_acc[j] = ctx_acc[j] * scale + p * rv[j];
                Mx = Mn;
                if (m < 24) {
#pragma unroll
                    for (int j = 0; j < 8; j++) rv[j] = nx[j];
                }
            }
#pragma unroll
            for (int j = 0; j < 8; j++) trp[warp * 256 + lane + 32 * j] = ctx_acc[j];
            if (lane == 0) { mden[warp * 2 + 0] = Mx; mden[warp * 2 + 1] = den; }
        }
        __syncthreads();
        if (tid < 8) {
            float M0 = mden[(2 * tid) * 2 + 0],     d0 = mden[(2 * tid) * 2 + 1];
            float M1 = mden[(2 * tid + 1) * 2 + 0], d1 = mden[(2 * tid + 1) * 2 + 1];
            float M = fmaxf(M0, M1);
            float s0 = __expf(M0 - M), s1 = __expf(M1 - M);
            float inv = 1.f / (d0 * s0 + d1 * s1);
            scb[tid * 2 + 0] = s0 * inv;
            scb[tid * 2 + 1] = s1 * inv;
        }
        __syncthreads();
#pragma unroll
        for (int p = 0; p < 4; p++) {
            int idx = tid + p * 512;
            int bb = idx >> 8, t = idx & 255;
            w_part[bb * 256 + t] = trp[(2 * bb) * 256 + t] * scb[bb * 2 + 0]
                                 + trp[(2 * bb + 1) * 256 + t] * scb[bb * 2 + 1];
        }
        __syncthreads();

        // e_c matvec (coalesced via g_W2t, k-split across groups)
        {
            float acc[8];
#pragma unroll
            for (int bb = 0; bb < 8; bb++) acc[bb] = 0.f;
            const int k0 = grp * 128;
            for (int k = k0; k < k0 + 128; k += 4) {
                float w0 = g_W2t[(k + 0) * 256 + t2];
                float w1 = g_W2t[(k + 1) * 256 + t2];
                float w2 = g_W2t[(k + 2) * 256 + t2];
                float w3 = g_W2t[(k + 3) * 256 + t2];
#pragma unroll
                for (int bb = 0; bb < 8; bb++) {
                    const float4 cv = *reinterpret_cast<const float4*>(&w_part[bb * 256 + k]);
                    acc[bb] += w0 * cv.x + w1 * cv.y + w2 * cv.z + w3 * cv.w;
                }
            }
#pragma unroll
            for (int bb = 0; bb < 8; bb++) trp[(grp * 8 + bb) * 256 + t2] = acc[bb];
        }
        __syncthreads();

        float ec[8];
        if (tid < 256) {
            float bias = W2_b[t2];
#pragma unroll
            for (int bb = 0; bb < 8; bb++) {
                ec[bb] = trp[bb * 256 + t2] + trp[(8 + bb) * 256 + t2] + bias;
                if (aux) __stcs(&aux[3 * 262144 + (size_t)(b0 + bb) * RANK + t2], ec[bb]);
            }
            float uo = Uo_w[t2], wo = Wo_w[t2];
#pragma unroll
            for (int bb = 0; bb < 8; bb++) {
                float c = uo * lr_sm[bb * 256 + t2] + wo * ec[bb];
#pragma unroll
                for (int o = 16; o > 0; o >>= 1) c += __shfl_xor_sync(0xffffffffu, c, o);
                if (lane == 0) red[bb * 8 + warp] = c;
            }
        }
        __syncthreads();
        if (tid < 8) {
            float s = 0.f;
#pragma unroll
            for (int w = 0; w < 8; w++) s += red[tid * 8 + w];
            s += Uo_b[0] + Wo_b[0];
            g_sm[tid] = 1.f / (1.f + expf(-s));
        }
        __syncthreads();
        if (tid < 256) {
#pragma unroll
            for (int bb = 0; bb < 8; bb++) {
                float g = g_sm[bb];
                float q = lr_sm[bb * 256 + t2] * (g * ec[bb] + 1.f - g);
                g_q16[(size_t)(b0 + bb) * RANK + t2] = __float2half_rn(q * QSCALE);
            }
        }
        __threadfence();
        __syncthreads();
        if (tid == 0) atomicAdd(&g_flag_q[blockIdx.x >> 4], 1);
    }

    // ===================== Phase 2: convert queue (all CTAs) ================
    for (;;) {
        __syncthreads();
        if (tid == 0) cu = atomicAdd(&g_conv_ctr, 1u);
        __syncthreads();
        unsigned u = cu;
        if (u >= (unsigned)NBT) break;
        int r0 = (int)u * 256;
        int nrows = NENT - r0;
        if (nrows > 256) nrows = 256;
        for (int i = tid; i < nrows * 32; i += 512) {
            int row = i >> 5, c8 = (i & 31) * 8;
            size_t base = (size_t)(r0 + row) * RANK + c8;
            float4 v0 = __ldcs(reinterpret_cast<const float4*>(rhs_w + base));
            float4 v1 = __ldcs(reinterpret_cast<const float4*>(rhs_w + base + 4));
            __half2 h[4];
            h[0] = __floats2half2_rn(v0.x * RSCALE, v0.y * RSCALE);
            h[1] = __floats2half2_rn(v0.z * RSCALE, v0.w * RSCALE);
            h[2] = __floats2half2_rn(v1.x * RSCALE, v1.y * RSCALE);
            h[3] = __floats2half2_rn(v1.z * RSCALE, v1.w * RSCALE);
            *reinterpret_cast<uint4*>(g_rhs16 + base) = *reinterpret_cast<uint4*>(h);
        }
        __threadfence();
        __syncthreads();
        if (tid == 0) atomicExch(&g_flag_b[u], 1);
    }

    // ===================== Phase 3: persistent GEMM (all CTAs) ==============
    const int wm = warp & 1;     // m offset 64*wm
    const int wn = warp >> 1;    // n offset 32*wn
    const int gid = lane >> 2;
    const int qid = lane & 3;
    const int lrow = lane & 15;
    const int lcol16 = (lane >> 4) * 16;

    const uint32_t smem_u32 = (uint32_t)__cvta_generic_to_shared(dynsm);
    const uint32_t mbar0 = smem_u32;

    const int nct = gridDim.x;
    const int nloc = (NT - (int)blockIdx.x + nct - 1) / nct;
    if (nloc <= 0) return;
    const int Ltot = 2 * nloc;

    auto wait_tile = [&](int t) {   // tid 0 only
        int mt = t & 7, nt = t >> 3;
        while (ld_acquire(&g_flag_q[mt]) < 16) {}
        while (ld_acquire(&g_flag_b[nt]) == 0) {}
    };
    auto issue_chunk = [&](int L) {
        const int li = L >> 1, ch = L & 1;
        const int t = (int)blockIdx.x + li * nct;
        const int m0 = (t & 7) * BM;
        const int n0 = (t >> 3) * BN;
        const uint32_t sb = smem_u32 + SM_CTRL + (uint32_t)(ch * STG_BYTES);
        const uint32_t mb = mbar0 + ch * 8;
        if (tid < BM)
            bulk_cp(sb + (uint32_t)(tid * KP * 2),
                    g_q16 + (size_t)(m0 + tid) * RANK + ch * BKC, ROW_BYTES, mb);
        if (tid < BN) {
            int nr = n0 + tid;
            if (nr > NENT - 1) nr = NENT - 1;
            bulk_cp(sb + A_STG + (uint32_t)(tid * KP * 2),
                    g_rhs16 + (size_t)nr * RANK + ch * BKC, ROW_BYTES, mb);
        }
    };

    __syncthreads();
    if (tid == 0) {
        MBARRIER_INIT(mbar0 + 0, 1);
        MBARRIER_INIT(mbar0 + 8, 1);
    }
    __syncthreads();
    if (tid == 0) {
        wait_tile((int)blockIdx.x);
        MBARRIER_EXPECT_TX(mbar0 + 0, CHUNK_TX);
        if (Ltot > 1) MBARRIER_EXPECT_TX(mbar0 + 8, CHUNK_TX);
    }
    __syncthreads();
    issue_chunk(0);
    if (Ltot > 1) issue_chunk(1);

#pragma unroll 1
    for (int li = 0; li < nloc; li++) {
        const int t = (int)blockIdx.x + li * nct;
        const int m0 = (t & 7) * BM;
        const int n0 = (t >> 3) * BN;

        float acc[4][4][4];
#pragma unroll
        for (int i = 0; i < 4; i++)
#pragma unroll
            for (int f = 0; f < 4; f++)
#pragma unroll
                for (int r = 0; r < 4; r++) acc[i][f][r] = 0.f;

#pragma unroll 1
        for (int ch = 0; ch < 2; ch++) {
            const int L = li * 2 + ch;
            MBARRIER_WAIT_PARITY(mbar0 + ch * 8, li & 1);

            const uint32_t abase = smem_u32 + SM_CTRL + (uint32_t)(ch * STG_BYTES);
            const uint32_t bbase = abase + A_STG;
#pragma unroll
            for (int kk = 0; kk < BKC / 16; kk++) {
                uint32_t a[4][4];
#pragma unroll
                for (int i = 0; i < 4; i++)
                    ldsm_x4(a[i], abase + (uint32_t)((wm * 64 + i * 16 + lrow) * (KP * 2)
                                                     + kk * 32 + lcol16));
                uint32_t b[2][4];
#pragma unroll
                for (int j = 0; j < 2; j++)
                    ldsm_x4(b[j], bbase + (uint32_t)((wn * 32 + j * 16 + lrow) * (KP * 2)
                                                     + kk * 32 + lcol16));
#pragma unroll
                for (int i = 0; i < 4; i++)
#pragma unroll
                    for (int f = 0; f < 4; f++) {
                        int j = f >> 1, h = f & 1;
                        mma_f16(acc[i][f], a[i], b[j][h], b[j][h + 2]);
                    }
            }

            if (L + 2 < Ltot) {
                __syncthreads();
                if (tid == 0) {
                    if (ch == 0) wait_tile((int)blockIdx.x + (li + 1) * nct);
                    MBARRIER_EXPECT_TX(mbar0 + ch * 8, CHUNK_TX);
                }
                __syncthreads();
                issue_chunk(L + 2);
            }
        }

        // epilogue: descale + streaming stores
#pragma unroll
        for (int i = 0; i < 4; i++) {
            int r = m0 + wm * 64 + i * 16 + gid;
#pragma unroll
            for (int f = 0; f < 4; f++) {
                int cb = n0 + wn * 32 + f * 8 + 2 * qid;
                if (cb < NENT) {
                    __stcs(reinterpret_cast<float2*>(out + (size_t)r * NENT + cb),
                           make_float2(acc[i][f][0] * OSCALE, acc[i][f][1] * OSCALE));
                    __stcs(reinterpret_cast<float2*>(out + (size_t)(r + 8) * NENT + cb),
                           make_float2(acc[i][f][2] * OSCALE, acc[i][f][3] * OSCALE));
                }
            }
        }
    }
}

// ---------------------------------------------------------------------------
extern "C" void kernel_launch(void* const* d_in, const int* in_sizes, int n_in,
                              void* d_out, int out_size) {
    const int*   x      = (const int*)d_in[0];
    const int*   nb     = (const int*)d_in[1];
    const float* lhs_w  = (const float*)d_in[2];
    const float* rel_w  = (const float*)d_in[3];
    const float* rhs_w  = (const float*)d_in[4];
    const float* W_w    = (const float*)d_in[5];
    const float* W_b    = (const float*)d_in[6];
    const float* W2_w   = (const float*)d_in[7];
    const float* W2_b   = (const float*)d_in[8];
    const float* Wo_w   = (const float*)d_in[9];
    const float* Wo_b   = (const float*)d_in[10];
    const float* Uo_w   = (const float*)d_in[11];
    const float* Uo_b   = (const float*)d_in[12];
    float* out = (float*)d_out;

    float* aux = nullptr;
    if (out_size >= 102400000 + 4 * 262144) aux = out + 102400000;

    static int nsm = 0;
    if (!nsm) {
        cudaFuncSetAttribute(fused_kernel,
                             cudaFuncAttributeMaxDynamicSharedMemorySize, SMEM_BYTES);
        int dev = 0;
        cudaGetDevice(&dev);
        cudaDeviceGetAttribute(&nsm, cudaDevAttrMultiProcessorCount, dev);
        if (nsm <= 0) nsm = 148;
        if (nsm > 1024) nsm = 1024;
    }

    setup_kernel<<<(512 * 256 + 256 * 256 + 255) / 256, 256>>>(W_w, W2_w);
    fused_kernel<<<nsm, 512, SMEM_BYTES>>>(x, nb, lhs_w, rel_w, rhs_w,
                                           W_b, W2_b, Wo_w, Wo_b, Uo_b ? Uo_w : Uo_w, Uo_b, out, aux);
}